// round 1
// baseline (speedup 1.0000x reference)
#include <cuda_runtime.h>
#include <math.h>

#define B_   2
#define L_   4096
#define C_   1024
#define H_   16
#define D_   64
#define WIN_ 128
#define NB_  (L_ / WIN_)
#define M_   (B_ * L_)   // 8192 rows

// Scratch (device globals — no allocation allowed)
__device__ float g_q[(size_t)M_ * C_];
__device__ float g_k[(size_t)M_ * C_];
__device__ float g_v[(size_t)M_ * C_];
__device__ float g_att[(size_t)M_ * C_];

// ---------------------------------------------------------------------------
// SGEMM: C[M,N] = A[M,K] @ W[K,N] + bias[N]
// 128x128 tile, BK=8, 256 threads, 8x8 per-thread microtile, double-buffered
// M,N multiples of 128; K multiple of 8 (true here: 8192/1024/1024).
// ---------------------------------------------------------------------------
__global__ __launch_bounds__(256)
void sgemm_bias_kernel(const float* __restrict__ A,
                       const float* __restrict__ W,
                       const float* __restrict__ bias,
                       float* __restrict__ Cm,
                       int M, int N, int K)
{
    const int BM = 128, BN = 128, BK = 8;
    __shared__ float As[2][BK][BM];
    __shared__ float Bs[2][BK][BN];

    const int tid  = threadIdx.x;
    const int tx   = tid & 15;        // 0..15  (N dir)
    const int ty   = tid >> 4;        // 0..15  (M dir)
    const int row0 = blockIdx.y * BM;
    const int col0 = blockIdx.x * BN;

    const int aRow = tid >> 1;        // 0..127
    const int aCol = (tid & 1) * 4;   // 0 or 4
    const int bRow = tid >> 5;        // 0..7
    const int bCol = (tid & 31) * 4;  // 0..124

    float acc[8][8];
    #pragma unroll
    for (int i = 0; i < 8; i++)
        #pragma unroll
        for (int j = 0; j < 8; j++)
            acc[i][j] = 0.0f;

    // prologue: load tile 0 into buffer 0
    {
        float4 a4 = *(const float4*)(A + (size_t)(row0 + aRow) * K + aCol);
        As[0][aCol + 0][aRow] = a4.x;
        As[0][aCol + 1][aRow] = a4.y;
        As[0][aCol + 2][aRow] = a4.z;
        As[0][aCol + 3][aRow] = a4.w;
        float4 b4 = *(const float4*)(W + (size_t)bRow * N + col0 + bCol);
        *(float4*)&Bs[0][bRow][bCol] = b4;
    }
    __syncthreads();

    int buf = 0;
    for (int k0 = BK; k0 <= K; k0 += BK) {
        int nbuf = buf ^ 1;
        if (k0 < K) {
            float4 a4 = *(const float4*)(A + (size_t)(row0 + aRow) * K + k0 + aCol);
            As[nbuf][aCol + 0][aRow] = a4.x;
            As[nbuf][aCol + 1][aRow] = a4.y;
            As[nbuf][aCol + 2][aRow] = a4.z;
            As[nbuf][aCol + 3][aRow] = a4.w;
            float4 b4 = *(const float4*)(W + (size_t)(k0 + bRow) * N + col0 + bCol);
            *(float4*)&Bs[nbuf][bRow][bCol] = b4;
        }
        #pragma unroll
        for (int kk = 0; kk < BK; kk++) {
            float af[8], bf[8];
            #pragma unroll
            for (int i = 0; i < 8; i += 4) {
                float4 f = *(const float4*)&As[buf][kk][ty * 8 + i];
                af[i] = f.x; af[i+1] = f.y; af[i+2] = f.z; af[i+3] = f.w;
            }
            #pragma unroll
            for (int j = 0; j < 8; j += 4) {
                float4 f = *(const float4*)&Bs[buf][kk][tx * 8 + j];
                bf[j] = f.x; bf[j+1] = f.y; bf[j+2] = f.z; bf[j+3] = f.w;
            }
            #pragma unroll
            for (int i = 0; i < 8; i++)
                #pragma unroll
                for (int j = 0; j < 8; j++)
                    acc[i][j] = fmaf(af[i], bf[j], acc[i][j]);
        }
        __syncthreads();
        buf = nbuf;
    }

    // epilogue + bias
    #pragma unroll
    for (int i = 0; i < 8; i++) {
        size_t r = (size_t)(row0 + ty * 8 + i);
        #pragma unroll
        for (int j = 0; j < 8; j += 4) {
            int c = col0 + tx * 8 + j;
            float4 b4 = *(const float4*)(bias + c);
            float4 o4;
            o4.x = acc[i][j + 0] + b4.x;
            o4.y = acc[i][j + 1] + b4.y;
            o4.z = acc[i][j + 2] + b4.z;
            o4.w = acc[i][j + 3] + b4.w;
            *(float4*)(Cm + r * N + c) = o4;
        }
    }
}

// ---------------------------------------------------------------------------
// Sliding-window attention (flash-style online softmax).
// Grid: (NB_, H_, B_). Block: 128 threads = one query row each.
// Reference semantics: band mask |kpos - p| <= WIN (inclusive); keys outside
// the sequence but inside the band are ZERO vectors (score 0, v = 0), and they
// DO count in the softmax denominator. Reproduced by zero-filling smem rows.
// ---------------------------------------------------------------------------
__global__ __launch_bounds__(128)
void attn_kernel(const float* __restrict__ q,
                 const float* __restrict__ k,
                 const float* __restrict__ v,
                 float* __restrict__ out)
{
    extern __shared__ float smem[];
    float* ks = smem;                     // [WIN_][D_]
    float* vs = smem + WIN_ * D_;         // [WIN_][D_]

    const int blk = blockIdx.x;
    const int h   = blockIdx.y;
    const int b   = blockIdx.z;
    const int t   = threadIdx.x;
    const int p   = blk * WIN_ + t;       // global query position in sequence

    // load my q row into registers
    float qr[D_];
    const float* qp = q + ((size_t)(b * L_ + p)) * C_ + h * D_;
    #pragma unroll
    for (int d = 0; d < D_; d += 4) {
        float4 f = *(const float4*)(qp + d);
        qr[d] = f.x; qr[d+1] = f.y; qr[d+2] = f.z; qr[d+3] = f.w;
    }

    float m = -INFINITY;
    float l = 0.0f;
    float o[D_];
    #pragma unroll
    for (int d = 0; d < D_; d++) o[d] = 0.0f;

    const float scale = 0.125f;           // 1/sqrt(64)

    for (int c = -1; c <= 1; c++) {
        const int base = blk * WIN_ + c * WIN_;   // key-chunk base (may be <0 or >=L)

        __syncthreads();   // everyone done with previous chunk before overwrite
        // cooperative load: 128 rows x 64 floats = 2048 float4, 128 threads
        for (int i = t; i < WIN_ * (D_ / 4); i += 128) {
            int r  = i >> 4;
            int dc = (i & 15) << 2;
            int kp = base + r;
            float4 kf = make_float4(0.f, 0.f, 0.f, 0.f);
            float4 vf = make_float4(0.f, 0.f, 0.f, 0.f);
            if (kp >= 0 && kp < L_) {
                size_t off = ((size_t)(b * L_ + kp)) * C_ + h * D_ + dc;
                kf = *(const float4*)(k + off);
                vf = *(const float4*)(v + off);
            }
            *(float4*)&ks[r * D_ + dc] = kf;
            *(float4*)&vs[r * D_ + dc] = vf;
        }
        __syncthreads();

        // process 128 keys in sub-tiles of 16
        for (int j0 = 0; j0 < WIN_; j0 += 16) {
            float s[16];
            float cmax = -INFINITY;
            #pragma unroll
            for (int j = 0; j < 16; j++) {
                const float4* kr = (const float4*)&ks[(j0 + j) * D_];
                float a0 = 0.f, a1 = 0.f, a2 = 0.f, a3 = 0.f;
                #pragma unroll
                for (int d4 = 0; d4 < D_ / 4; d4++) {
                    float4 kf = kr[d4];
                    a0 = fmaf(qr[4*d4+0], kf.x, a0);
                    a1 = fmaf(qr[4*d4+1], kf.y, a1);
                    a2 = fmaf(qr[4*d4+2], kf.z, a2);
                    a3 = fmaf(qr[4*d4+3], kf.w, a3);
                }
                float sc = ((a0 + a1) + (a2 + a3)) * scale;
                int diff = base + j0 + j - p;
                if (diff < -WIN_ || diff > WIN_) sc = -INFINITY;  // band mask only
                s[j] = sc;
                cmax = fmaxf(cmax, sc);
            }
            float mnew = fmaxf(m, cmax);
            if (mnew == -INFINITY) continue;      // whole sub-tile banded out
            float corr = __expf(m - mnew);        // exp(-inf)=0 handles first tile
            m = mnew;
            l *= corr;
            #pragma unroll
            for (int d = 0; d < D_; d++) o[d] *= corr;
            #pragma unroll
            for (int j = 0; j < 16; j++) {
                float pj = __expf(s[j] - mnew);   // s=-inf -> 0
                l += pj;
                const float4* vr = (const float4*)&vs[(j0 + j) * D_];
                #pragma unroll
                for (int d4 = 0; d4 < D_ / 4; d4++) {
                    float4 vf = vr[d4];
                    o[4*d4+0] = fmaf(pj, vf.x, o[4*d4+0]);
                    o[4*d4+1] = fmaf(pj, vf.y, o[4*d4+1]);
                    o[4*d4+2] = fmaf(pj, vf.z, o[4*d4+2]);
                    o[4*d4+3] = fmaf(pj, vf.w, o[4*d4+3]);
                }
            }
        }
    }

    const float inv = 1.0f / l;
    float* op = out + ((size_t)(b * L_ + p)) * C_ + h * D_;
    #pragma unroll
    for (int d = 0; d < D_; d += 4) {
        float4 o4;
        o4.x = o[d+0] * inv; o4.y = o[d+1] * inv;
        o4.z = o[d+2] * inv; o4.w = o[d+3] * inv;
        *(float4*)(op + d) = o4;
    }
}

// ---------------------------------------------------------------------------
extern "C" void kernel_launch(void* const* d_in, const int* in_sizes, int n_in,
                              void* d_out, int out_size)
{
    const float* x  = (const float*)d_in[0];
    const float* wq = (const float*)d_in[1];
    const float* bq = (const float*)d_in[2];
    const float* wk = (const float*)d_in[3];
    const float* bk = (const float*)d_in[4];
    const float* wv = (const float*)d_in[5];
    const float* bv = (const float*)d_in[6];
    const float* wo = (const float*)d_in[7];
    const float* bo = (const float*)d_in[8];
    float* out = (float*)d_out;

    float *q, *k, *v, *att;
    cudaGetSymbolAddress((void**)&q,   g_q);
    cudaGetSymbolAddress((void**)&k,   g_k);
    cudaGetSymbolAddress((void**)&v,   g_v);
    cudaGetSymbolAddress((void**)&att, g_att);

    dim3 gGrid(C_ / 128, M_ / 128);   // (8, 64)
    dim3 gBlk(256);

    sgemm_bias_kernel<<<gGrid, gBlk>>>(x, wq, bq, q, M_, C_, C_);
    sgemm_bias_kernel<<<gGrid, gBlk>>>(x, wk, bk, k, M_, C_, C_);
    sgemm_bias_kernel<<<gGrid, gBlk>>>(x, wv, bv, v, M_, C_, C_);

    int smem = 2 * WIN_ * D_ * sizeof(float);   // 64 KB
    cudaFuncSetAttribute(attn_kernel, cudaFuncAttributeMaxDynamicSharedMemorySize, smem);
    dim3 aGrid(NB_, H_, B_);
    attn_kernel<<<aGrid, 128, smem>>>(q, k, v, att);

    sgemm_bias_kernel<<<gGrid, gBlk>>>(att, wo, bo, out, M_, C_, C_);
}

// round 3
// speedup vs baseline: 2.2419x; 2.2419x over previous
#include <cuda_runtime.h>
#include <math.h>
#include <stdint.h>

#define B_   2
#define L_   4096
#define C_   1024
#define H_   16
#define D_   64
#define WIN_ 128
#define NB_  (L_ / WIN_)
#define M_   (B_ * L_)   // 8192 rows

// ---------------- scratch (device globals; no allocation allowed) ----------
__device__ float g_q  [(size_t)M_ * C_];
__device__ float g_k  [(size_t)M_ * C_];
__device__ float g_v  [(size_t)M_ * C_];
__device__ float g_att[(size_t)M_ * C_];
__device__ float g_xa [(size_t)M_ * C_];    // x converted to tf32 (rna)
__device__ float g_ata[(size_t)M_ * C_];    // att converted to tf32 (rna)
__device__ float g_wt [4][(size_t)C_ * C_]; // transposed+rna weights [N][K]

// ---------------------------------------------------------------------------
// helpers
// ---------------------------------------------------------------------------
__device__ __forceinline__ uint32_t smem_u32(const void* p) {
    uint32_t a;
    asm("{ .reg .u64 t; cvta.to.shared.u64 t, %1; cvt.u32.u64 %0, t; }"
        : "=r"(a) : "l"(p));
    return a;
}
__device__ __forceinline__ float rna_tf32(float f) {
    uint32_t u;
    asm("cvt.rna.tf32.f32 %0, %1;" : "=r"(u) : "f"(f));
    return __uint_as_float(u);
}
__device__ __forceinline__ void cp_async16(uint32_t dst, const void* src) {
    asm volatile("cp.async.cg.shared.global [%0], [%1], 16;"
                 :: "r"(dst), "l"(src) : "memory");
}
__device__ __forceinline__ void cp_commit() {
    asm volatile("cp.async.commit_group;" ::: "memory");
}
__device__ __forceinline__ void mma_tf32_16x8x8(float c[4],
                                                const uint32_t a[4],
                                                uint32_t b0, uint32_t b1) {
    asm volatile(
        "mma.sync.aligned.m16n8k8.row.col.f32.tf32.tf32.f32 "
        "{%0,%1,%2,%3}, {%4,%5,%6,%7}, {%8,%9}, {%0,%1,%2,%3};"
        : "+f"(c[0]), "+f"(c[1]), "+f"(c[2]), "+f"(c[3])
        : "r"(a[0]), "r"(a[1]), "r"(a[2]), "r"(a[3]), "r"(b0), "r"(b1));
}

// ---------------------------------------------------------------------------
// elementwise rna-convert (fp32 -> tf32-rounded fp32 bits)
// ---------------------------------------------------------------------------
__global__ void cvt_rna_kernel(const float* __restrict__ in, float* __restrict__ out) {
    size_t i = ((size_t)blockIdx.x * blockDim.x + threadIdx.x) * 4;
    float4 v = *(const float4*)(in + i);
    v.x = rna_tf32(v.x); v.y = rna_tf32(v.y);
    v.z = rna_tf32(v.z); v.w = rna_tf32(v.w);
    *(float4*)(out + i) = v;
}

// transpose W[K,N] -> Wt[N,K] with rna rounding (K=N=1024)
__global__ void transpose_cvt_kernel(const float* __restrict__ W, float* __restrict__ Wt) {
    __shared__ float tile[32][33];
    int x = blockIdx.x * 32 + threadIdx.x;   // n
    int y = blockIdx.y * 32 + threadIdx.y;   // k
    #pragma unroll
    for (int dy = 0; dy < 32; dy += 8)
        tile[threadIdx.y + dy][threadIdx.x] = W[(size_t)(y + dy) * C_ + x];
    __syncthreads();
    int nx = blockIdx.y * 32 + threadIdx.x;  // k
    int ny = blockIdx.x * 32 + threadIdx.y;  // n
    #pragma unroll
    for (int dy = 0; dy < 32; dy += 8)
        Wt[(size_t)(ny + dy) * C_ + nx] = rna_tf32(tile[threadIdx.x][threadIdx.y + dy]);
}

// ---------------------------------------------------------------------------
// tf32 mma.sync GEMM: Cm[M,1024] = A[M,1024] @ Wt^T + bias
//   A   : [M][K]  K-major (tf32-rounded fp32)
//   Wt  : [N][K]  K-major (tf32-rounded fp32)
//   128x128 tile, BK=32, 3-stage cp.async, 8 warps (4M x 2N), warp = 32x64
// ---------------------------------------------------------------------------
#define GBM 128
#define GBN 128
#define GBK 32
#define GSTG 3
#define GLD 36                               // padded stride in floats
#define GST_FLOATS ((GBM + GBN) * GLD)       // per-stage floats (A then B)
#define GSMEM_BYTES (GSTG * GST_FLOATS * 4)  // 110592
#define GNT (C_ / GBK)                       // 32 k-tiles

__device__ __forceinline__ void g_load_stage(const float* __restrict__ A,
                                             const float* __restrict__ Wt,
                                             int row0, int col0, int kt,
                                             uint32_t sstage, int tid)
{
    const int kf = kt * GBK;
    uint32_t aBase = sstage;
    uint32_t bBase = sstage + GBM * GLD * 4;
    #pragma unroll
    for (int it = 0; it < 8; it++) {
        int i = tid + it * 256;               // 0..2047
        if (i < GBM * 8) {
            int r = i >> 3, c = i & 7;
            cp_async16(aBase + r * (GLD * 4) + c * 16,
                       A + (size_t)(row0 + r) * C_ + kf + c * 4);
        } else {
            int j = i - GBM * 8;
            int n = j >> 3, c = j & 7;
            cp_async16(bBase + n * (GLD * 4) + c * 16,
                       Wt + (size_t)(col0 + n) * C_ + kf + c * 4);
        }
    }
    cp_commit();
}

__global__ __launch_bounds__(256)
void gemm_tf32_kernel(const float* __restrict__ A,
                      const float* __restrict__ Wt,
                      const float* __restrict__ bias,
                      float* __restrict__ Cm)
{
    extern __shared__ float sm[];
    const int tid    = threadIdx.x;
    const int lane   = tid & 31;
    const int wid    = tid >> 5;
    const int warp_m = wid & 3;               // 0..3
    const int warp_n = wid >> 2;               // 0..1
    const int grp    = lane >> 2;               // 0..7
    const int tig    = lane & 3;                // 0..3
    const int row0   = blockIdx.y * GBM;
    const int col0   = blockIdx.x * GBN;

    const uint32_t sbase = smem_u32(sm);
    const float* As = sm;                        // per-stage offset added below
    const float* Bs = sm + GBM * GLD;

    float cf[2][8][4];
    #pragma unroll
    for (int mt = 0; mt < 2; mt++)
        #pragma unroll
        for (int nt = 0; nt < 8; nt++)
            #pragma unroll
            for (int r = 0; r < 4; r++)
                cf[mt][nt][r] = 0.0f;

    // prologue: stage tiles 0..GSTG-2
    #pragma unroll
    for (int s = 0; s < GSTG - 1; s++)
        g_load_stage(A, Wt, row0, col0, s, sbase + s * GST_FLOATS * 4, tid);

    for (int t = 0; t < GNT; t++) {
        asm volatile("cp.async.wait_group %0;" :: "n"(GSTG - 2));
        __syncthreads();

        // issue next tile into the buffer freed at iter t-1
        int j = t + GSTG - 1;
        if (j < GNT)
            g_load_stage(A, Wt, row0, col0, j,
                         sbase + (j % GSTG) * GST_FLOATS * 4, tid);
        else
            cp_commit();   // keep group counting consistent

        // compute on buffer t % GSTG
        const float* as = As + (t % GSTG) * GST_FLOATS;
        const float* bs = Bs + (t % GSTG) * GST_FLOATS;

        #pragma unroll
        for (int ks = 0; ks < 4; ks++) {
            const int k0 = ks * 8;
            uint32_t af[2][4];
            #pragma unroll
            for (int mt = 0; mt < 2; mt++) {
                const float* ap = as + (warp_m * 32 + mt * 16 + grp) * GLD + k0 + tig;
                af[mt][0] = __float_as_uint(ap[0]);
                af[mt][1] = __float_as_uint(ap[8 * GLD]);
                af[mt][2] = __float_as_uint(ap[4]);
                af[mt][3] = __float_as_uint(ap[8 * GLD + 4]);
            }
            #pragma unroll
            for (int nt = 0; nt < 8; nt++) {
                const float* bp = bs + (warp_n * 64 + nt * 8 + grp) * GLD + k0 + tig;
                uint32_t b0 = __float_as_uint(bp[0]);
                uint32_t b1 = __float_as_uint(bp[4]);
                mma_tf32_16x8x8(cf[0][nt], af[0], b0, b1);
                mma_tf32_16x8x8(cf[1][nt], af[1], b0, b1);
            }
        }
        __syncthreads();
    }

    // epilogue + bias
    #pragma unroll
    for (int mt = 0; mt < 2; mt++) {
        int rbase = row0 + warp_m * 32 + mt * 16 + grp;
        #pragma unroll
        for (int nt = 0; nt < 8; nt++) {
            int col = col0 + warp_n * 64 + nt * 8 + tig * 2;
            float2 b2 = *(const float2*)(bias + col);
            float2 o0, o1;
            o0.x = cf[mt][nt][0] + b2.x;  o0.y = cf[mt][nt][1] + b2.y;
            o1.x = cf[mt][nt][2] + b2.x;  o1.y = cf[mt][nt][3] + b2.y;
            *(float2*)(Cm + (size_t)rbase * C_ + col)       = o0;
            *(float2*)(Cm + (size_t)(rbase + 8) * C_ + col) = o1;
        }
    }
}

// ---------------------------------------------------------------------------
// Sliding-window attention (unchanged; 542us — next optimization target)
// ---------------------------------------------------------------------------
__global__ __launch_bounds__(128)
void attn_kernel(const float* __restrict__ q,
                 const float* __restrict__ k,
                 const float* __restrict__ v,
                 float* __restrict__ out)
{
    extern __shared__ float smem[];
    float* ks = smem;
    float* vs = smem + WIN_ * D_;

    const int blk = blockIdx.x;
    const int h   = blockIdx.y;
    const int b   = blockIdx.z;
    const int t   = threadIdx.x;
    const int p   = blk * WIN_ + t;

    float qr[D_];
    const float* qp = q + ((size_t)(b * L_ + p)) * C_ + h * D_;
    #pragma unroll
    for (int d = 0; d < D_; d += 4) {
        float4 f = *(const float4*)(qp + d);
        qr[d] = f.x; qr[d+1] = f.y; qr[d+2] = f.z; qr[d+3] = f.w;
    }

    float m = -INFINITY;
    float l = 0.0f;
    float o[D_];
    #pragma unroll
    for (int d = 0; d < D_; d++) o[d] = 0.0f;

    const float scale = 0.125f;

    for (int c = -1; c <= 1; c++) {
        const int base = blk * WIN_ + c * WIN_;

        __syncthreads();
        for (int i = t; i < WIN_ * (D_ / 4); i += 128) {
            int r  = i >> 4;
            int dc = (i & 15) << 2;
            int kp = base + r;
            float4 kf = make_float4(0.f, 0.f, 0.f, 0.f);
            float4 vf = make_float4(0.f, 0.f, 0.f, 0.f);
            if (kp >= 0 && kp < L_) {
                size_t off = ((size_t)(b * L_ + kp)) * C_ + h * D_ + dc;
                kf = *(const float4*)(k + off);
                vf = *(const float4*)(v + off);
            }
            *(float4*)&ks[r * D_ + dc] = kf;
            *(float4*)&vs[r * D_ + dc] = vf;
        }
        __syncthreads();

        for (int j0 = 0; j0 < WIN_; j0 += 16) {
            float s[16];
            float cmax = -INFINITY;
            #pragma unroll
            for (int j = 0; j < 16; j++) {
                const float4* kr = (const float4*)&ks[(j0 + j) * D_];
                float a0 = 0.f, a1 = 0.f, a2 = 0.f, a3 = 0.f;
                #pragma unroll
                for (int d4 = 0; d4 < D_ / 4; d4++) {
                    float4 kf = kr[d4];
                    a0 = fmaf(qr[4*d4+0], kf.x, a0);
                    a1 = fmaf(qr[4*d4+1], kf.y, a1);
                    a2 = fmaf(qr[4*d4+2], kf.z, a2);
                    a3 = fmaf(qr[4*d4+3], kf.w, a3);
                }
                float sc = ((a0 + a1) + (a2 + a3)) * scale;
                int diff = base + j0 + j - p;
                if (diff < -WIN_ || diff > WIN_) sc = -INFINITY;
                s[j] = sc;
                cmax = fmaxf(cmax, sc);
            }
            float mnew = fmaxf(m, cmax);
            if (mnew == -INFINITY) continue;
            float corr = __expf(m - mnew);
            m = mnew;
            l *= corr;
            #pragma unroll
            for (int d = 0; d < D_; d++) o[d] *= corr;
            #pragma unroll
            for (int j = 0; j < 16; j++) {
                float pj = __expf(s[j] - mnew);
                l += pj;
                const float4* vr = (const float4*)&vs[(j0 + j) * D_];
                #pragma unroll
                for (int d4 = 0; d4 < D_ / 4; d4++) {
                    float4 vf = vr[d4];
                    o[4*d4+0] = fmaf(pj, vf.x, o[4*d4+0]);
                    o[4*d4+1] = fmaf(pj, vf.y, o[4*d4+1]);
                    o[4*d4+2] = fmaf(pj, vf.z, o[4*d4+2]);
                    o[4*d4+3] = fmaf(pj, vf.w, o[4*d4+3]);
                }
            }
        }
    }

    const float inv = 1.0f / l;
    float* op = out + ((size_t)(b * L_ + p)) * C_ + h * D_;
    #pragma unroll
    for (int d = 0; d < D_; d += 4) {
        float4 o4;
        o4.x = o[d+0] * inv; o4.y = o[d+1] * inv;
        o4.z = o[d+2] * inv; o4.w = o[d+3] * inv;
        *(float4*)(op + d) = o4;
    }
}

// ---------------------------------------------------------------------------
extern "C" void kernel_launch(void* const* d_in, const int* in_sizes, int n_in,
                              void* d_out, int out_size)
{
    const float* x  = (const float*)d_in[0];
    const float* wq = (const float*)d_in[1];
    const float* bq = (const float*)d_in[2];
    const float* wk = (const float*)d_in[3];
    const float* bk = (const float*)d_in[4];
    const float* wv = (const float*)d_in[5];
    const float* bv = (const float*)d_in[6];
    const float* wo = (const float*)d_in[7];
    const float* bo = (const float*)d_in[8];
    float* out = (float*)d_out;

    float *q, *k, *v, *att, *xa, *ata, *wt;
    cudaGetSymbolAddress((void**)&q,   g_q);
    cudaGetSymbolAddress((void**)&k,   g_k);
    cudaGetSymbolAddress((void**)&v,   g_v);
    cudaGetSymbolAddress((void**)&att, g_att);
    cudaGetSymbolAddress((void**)&xa,  g_xa);
    cudaGetSymbolAddress((void**)&ata, g_ata);
    cudaGetSymbolAddress((void**)&wt,  g_wt);
    float* wtq = wt + 0 * (size_t)C_ * C_;
    float* wtk = wt + 1 * (size_t)C_ * C_;
    float* wtv = wt + 2 * (size_t)C_ * C_;
    float* wto = wt + 3 * (size_t)C_ * C_;

    // input conversions
    cvt_rna_kernel<<<(M_ * C_) / 4 / 256, 256>>>(x, xa);
    dim3 tGrid(C_ / 32, C_ / 32), tBlk(32, 8);
    transpose_cvt_kernel<<<tGrid, tBlk>>>(wq, wtq);
    transpose_cvt_kernel<<<tGrid, tBlk>>>(wk, wtk);
    transpose_cvt_kernel<<<tGrid, tBlk>>>(wv, wtv);
    transpose_cvt_kernel<<<tGrid, tBlk>>>(wo, wto);

    cudaFuncSetAttribute(gemm_tf32_kernel,
                         cudaFuncAttributeMaxDynamicSharedMemorySize, GSMEM_BYTES);
    dim3 gGrid(C_ / GBN, M_ / GBM);   // (8, 64)

    gemm_tf32_kernel<<<gGrid, 256, GSMEM_BYTES>>>(xa, wtq, bq, q);
    gemm_tf32_kernel<<<gGrid, 256, GSMEM_BYTES>>>(xa, wtk, bk, k);
    gemm_tf32_kernel<<<gGrid, 256, GSMEM_BYTES>>>(xa, wtv, bv, v);

    int asmem = 2 * WIN_ * D_ * sizeof(float);
    cudaFuncSetAttribute(attn_kernel, cudaFuncAttributeMaxDynamicSharedMemorySize, asmem);
    dim3 aGrid(NB_, H_, B_);
    attn_kernel<<<aGrid, 128, asmem>>>(q, k, v, att);

    cvt_rna_kernel<<<(M_ * C_) / 4 / 256, 256>>>(att, ata);
    gemm_tf32_kernel<<<gGrid, 256, GSMEM_BYTES>>>(ata, wto, bo, out);
}

// round 4
// speedup vs baseline: 3.7320x; 1.6646x over previous
#include <cuda_runtime.h>
#include <math.h>
#include <stdint.h>

#define B_   2
#define L_   4096
#define C_   1024
#define H_   16
#define D_   64
#define WIN_ 128
#define NB_  (L_ / WIN_)
#define M_   (B_ * L_)   // 8192 rows

// ---------------- scratch (device globals; no allocation allowed) ----------
__device__ float g_q  [(size_t)M_ * C_];
__device__ float g_k  [(size_t)M_ * C_];
__device__ float g_v  [(size_t)M_ * C_];
__device__ float g_att[(size_t)M_ * C_];
__device__ float g_xa [(size_t)M_ * C_];    // x converted to tf32 (rna)
__device__ float g_wt [4][(size_t)C_ * C_]; // transposed+rna weights [N][K]

// ---------------------------------------------------------------------------
// helpers
// ---------------------------------------------------------------------------
__device__ __forceinline__ uint32_t smem_u32(const void* p) {
    uint32_t a;
    asm("{ .reg .u64 t; cvta.to.shared.u64 t, %1; cvt.u32.u64 %0, t; }"
        : "=r"(a) : "l"(p));
    return a;
}
__device__ __forceinline__ float rna_tf32(float f) {
    uint32_t u;
    asm("cvt.rna.tf32.f32 %0, %1;" : "=r"(u) : "f"(f));
    return __uint_as_float(u);
}
__device__ __forceinline__ void cp_async16(uint32_t dst, const void* src) {
    asm volatile("cp.async.cg.shared.global [%0], [%1], 16;"
                 :: "r"(dst), "l"(src) : "memory");
}
__device__ __forceinline__ void cp_async16z(uint32_t dst, const void* src, unsigned sz) {
    asm volatile("cp.async.cg.shared.global [%0], [%1], 16, %2;"
                 :: "r"(dst), "l"(src), "r"(sz) : "memory");
}
__device__ __forceinline__ void cp_commit() {
    asm volatile("cp.async.commit_group;" ::: "memory");
}
__device__ __forceinline__ void mma_tf32_16x8x8(float c[4],
                                                const uint32_t a[4],
                                                uint32_t b0, uint32_t b1) {
    asm volatile(
        "mma.sync.aligned.m16n8k8.row.col.f32.tf32.tf32.f32 "
        "{%0,%1,%2,%3}, {%4,%5,%6,%7}, {%8,%9}, {%0,%1,%2,%3};"
        : "+f"(c[0]), "+f"(c[1]), "+f"(c[2]), "+f"(c[3])
        : "r"(a[0]), "r"(a[1]), "r"(a[2]), "r"(a[3]), "r"(b0), "r"(b1));
}

// ---------------------------------------------------------------------------
// elementwise rna-convert (fp32 -> tf32-rounded fp32 bits)
// ---------------------------------------------------------------------------
__global__ void cvt_rna_kernel(const float* __restrict__ in, float* __restrict__ out) {
    size_t i = ((size_t)blockIdx.x * blockDim.x + threadIdx.x) * 4;
    float4 v = *(const float4*)(in + i);
    v.x = rna_tf32(v.x); v.y = rna_tf32(v.y);
    v.z = rna_tf32(v.z); v.w = rna_tf32(v.w);
    *(float4*)(out + i) = v;
}

// transpose W[K,N] -> Wt[N,K] with rna rounding (K=N=1024)
__global__ void transpose_cvt_kernel(const float* __restrict__ W, float* __restrict__ Wt) {
    __shared__ float tile[32][33];
    int x = blockIdx.x * 32 + threadIdx.x;   // n
    int y = blockIdx.y * 32 + threadIdx.y;   // k
    #pragma unroll
    for (int dy = 0; dy < 32; dy += 8)
        tile[threadIdx.y + dy][threadIdx.x] = W[(size_t)(y + dy) * C_ + x];
    __syncthreads();
    int nx = blockIdx.y * 32 + threadIdx.x;  // k
    int ny = blockIdx.x * 32 + threadIdx.y;  // n
    #pragma unroll
    for (int dy = 0; dy < 32; dy += 8)
        Wt[(size_t)(ny + dy) * C_ + nx] = rna_tf32(tile[threadIdx.x][threadIdx.y + dy]);
}

// ---------------------------------------------------------------------------
// tf32 mma.sync GEMM: Cm[M,1024] = A[M,1024] @ Wt^T + bias
//   (RNA template arg: round outputs to tf32 for downstream tensor consumers)
// ---------------------------------------------------------------------------
#define GBM 128
#define GBN 128
#define GBK 32
#define GSTG 3
#define GLD 36
#define GST_FLOATS ((GBM + GBN) * GLD)
#define GSMEM_BYTES (GSTG * GST_FLOATS * 4)
#define GNT (C_ / GBK)

__device__ __forceinline__ void g_load_stage(const float* __restrict__ A,
                                             const float* __restrict__ Wt,
                                             int row0, int col0, int kt,
                                             uint32_t sstage, int tid)
{
    const int kf = kt * GBK;
    uint32_t aBase = sstage;
    uint32_t bBase = sstage + GBM * GLD * 4;
    #pragma unroll
    for (int it = 0; it < 8; it++) {
        int i = tid + it * 256;
        if (i < GBM * 8) {
            int r = i >> 3, c = i & 7;
            cp_async16(aBase + r * (GLD * 4) + c * 16,
                       A + (size_t)(row0 + r) * C_ + kf + c * 4);
        } else {
            int j = i - GBM * 8;
            int n = j >> 3, c = j & 7;
            cp_async16(bBase + n * (GLD * 4) + c * 16,
                       Wt + (size_t)(col0 + n) * C_ + kf + c * 4);
        }
    }
    cp_commit();
}

template<bool RNA>
__global__ __launch_bounds__(256)
void gemm_tf32_kernel(const float* __restrict__ A,
                      const float* __restrict__ Wt,
                      const float* __restrict__ bias,
                      float* __restrict__ Cm)
{
    extern __shared__ float sm[];
    const int tid    = threadIdx.x;
    const int lane   = tid & 31;
    const int wid    = tid >> 5;
    const int warp_m = wid & 3;
    const int warp_n = wid >> 2;
    const int grp    = lane >> 2;
    const int tig    = lane & 3;
    const int row0   = blockIdx.y * GBM;
    const int col0   = blockIdx.x * GBN;

    const uint32_t sbase = smem_u32(sm);
    const float* As = sm;
    const float* Bs = sm + GBM * GLD;

    float cf[2][8][4];
    #pragma unroll
    for (int mt = 0; mt < 2; mt++)
        #pragma unroll
        for (int nt = 0; nt < 8; nt++)
            #pragma unroll
            for (int r = 0; r < 4; r++)
                cf[mt][nt][r] = 0.0f;

    #pragma unroll
    for (int s = 0; s < GSTG - 1; s++)
        g_load_stage(A, Wt, row0, col0, s, sbase + s * GST_FLOATS * 4, tid);

    for (int t = 0; t < GNT; t++) {
        asm volatile("cp.async.wait_group %0;" :: "n"(GSTG - 2));
        __syncthreads();

        int j = t + GSTG - 1;
        if (j < GNT)
            g_load_stage(A, Wt, row0, col0, j,
                         sbase + (j % GSTG) * GST_FLOATS * 4, tid);
        else
            cp_commit();

        const float* as = As + (t % GSTG) * GST_FLOATS;
        const float* bs = Bs + (t % GSTG) * GST_FLOATS;

        #pragma unroll
        for (int ks = 0; ks < 4; ks++) {
            const int k0 = ks * 8;
            uint32_t af[2][4];
            #pragma unroll
            for (int mt = 0; mt < 2; mt++) {
                const float* ap = as + (warp_m * 32 + mt * 16 + grp) * GLD + k0 + tig;
                af[mt][0] = __float_as_uint(ap[0]);
                af[mt][1] = __float_as_uint(ap[8 * GLD]);
                af[mt][2] = __float_as_uint(ap[4]);
                af[mt][3] = __float_as_uint(ap[8 * GLD + 4]);
            }
            #pragma unroll
            for (int nt = 0; nt < 8; nt++) {
                const float* bp = bs + (warp_n * 64 + nt * 8 + grp) * GLD + k0 + tig;
                uint32_t b0 = __float_as_uint(bp[0]);
                uint32_t b1 = __float_as_uint(bp[4]);
                mma_tf32_16x8x8(cf[0][nt], af[0], b0, b1);
                mma_tf32_16x8x8(cf[1][nt], af[1], b0, b1);
            }
        }
        __syncthreads();
    }

    #pragma unroll
    for (int mt = 0; mt < 2; mt++) {
        int rbase = row0 + warp_m * 32 + mt * 16 + grp;
        #pragma unroll
        for (int nt = 0; nt < 8; nt++) {
            int col = col0 + warp_n * 64 + nt * 8 + tig * 2;
            float2 b2 = *(const float2*)(bias + col);
            float2 o0, o1;
            if (RNA) {
                o0.x = rna_tf32(cf[mt][nt][0] + b2.x);  o0.y = rna_tf32(cf[mt][nt][1] + b2.y);
                o1.x = rna_tf32(cf[mt][nt][2] + b2.x);  o1.y = rna_tf32(cf[mt][nt][3] + b2.y);
            } else {
                o0.x = cf[mt][nt][0] + b2.x;  o0.y = cf[mt][nt][1] + b2.y;
                o1.x = cf[mt][nt][2] + b2.x;  o1.y = cf[mt][nt][3] + b2.y;
            }
            *(float2*)(Cm + (size_t)rbase * C_ + col)       = o0;
            *(float2*)(Cm + (size_t)(rbase + 8) * C_ + col) = o1;
        }
    }
}

// ---------------------------------------------------------------------------
// tensor-core flash attention
//   block = (win-block, head, batch), 256 threads (8 warps), warp = 16 q rows
//   chunk ci=0: keys blk-1 (mask c>=r); ci=1: blk (no mask); ci=2: blk+1 (c<=r)
//   OOB key rows zero-filled (they count in the softmax denominator — matches ref)
// ---------------------------------------------------------------------------
#define ALDQ 68
#define ALDK 68
#define ALDV 72
#define ASM_FLOATS (128 * ALDQ + 2 * 128 * (ALDK + ALDV))
#define ASM_BYTES  (ASM_FLOATS * 4)   // 178176

template<int CI>
__device__ __forceinline__ void attn_chunk(
    const float* __restrict__ Qs, const float* __restrict__ Ks,
    const float* __restrict__ Vs,
    int r0, int grp, int tig,
    float (&oc)[8][4], float& m0, float& m1, float& l0, float& l1)
{
    float scr[16][4];
    #pragma unroll
    for (int nt = 0; nt < 16; nt++)
        #pragma unroll
        for (int e = 0; e < 4; e++) scr[nt][e] = 0.f;

    // S = (Q/8) @ K^T
    #pragma unroll
    for (int ks = 0; ks < 8; ks++) {
        const float* qp = Qs + (r0 + grp) * ALDQ + ks * 8 + tig;
        uint32_t qa[4];
        qa[0] = __float_as_uint(qp[0]);
        qa[1] = __float_as_uint(qp[8 * ALDQ]);
        qa[2] = __float_as_uint(qp[4]);
        qa[3] = __float_as_uint(qp[8 * ALDQ + 4]);
        #pragma unroll
        for (int nt = 0; nt < 16; nt++) {
            const float* kp = Ks + (nt * 8 + grp) * ALDK + ks * 8 + tig;
            mma_tf32_16x8x8(scr[nt], qa,
                            __float_as_uint(kp[0]), __float_as_uint(kp[4]));
        }
    }

    const int ra = r0 + grp, rb = ra + 8;
    if (CI == 0) {
        #pragma unroll
        for (int nt = 0; nt < 16; nt++) {
            int c = nt * 8 + 2 * tig;
            if (c     < ra) scr[nt][0] = -INFINITY;
            if (c + 1 < ra) scr[nt][1] = -INFINITY;
            if (c     < rb) scr[nt][2] = -INFINITY;
            if (c + 1 < rb) scr[nt][3] = -INFINITY;
        }
    }
    if (CI == 2) {
        #pragma unroll
        for (int nt = 0; nt < 16; nt++) {
            int c = nt * 8 + 2 * tig;
            if (c     > ra) scr[nt][0] = -INFINITY;
            if (c + 1 > ra) scr[nt][1] = -INFINITY;
            if (c     > rb) scr[nt][2] = -INFINITY;
            if (c + 1 > rb) scr[nt][3] = -INFINITY;
        }
    }

    // online softmax (rows ra, rb live in a 4-lane quad)
    float mx0 = -INFINITY, mx1 = -INFINITY;
    #pragma unroll
    for (int nt = 0; nt < 16; nt++) {
        mx0 = fmaxf(mx0, fmaxf(scr[nt][0], scr[nt][1]));
        mx1 = fmaxf(mx1, fmaxf(scr[nt][2], scr[nt][3]));
    }
    mx0 = fmaxf(mx0, __shfl_xor_sync(0xffffffffu, mx0, 1));
    mx0 = fmaxf(mx0, __shfl_xor_sync(0xffffffffu, mx0, 2));
    mx1 = fmaxf(mx1, __shfl_xor_sync(0xffffffffu, mx1, 1));
    mx1 = fmaxf(mx1, __shfl_xor_sync(0xffffffffu, mx1, 2));

    float mn0 = fmaxf(m0, mx0), mn1 = fmaxf(m1, mx1);
    float cr0 = __expf(m0 - mn0), cr1 = __expf(m1 - mn1);
    m0 = mn0; m1 = mn1;
    l0 *= cr0; l1 *= cr1;
    #pragma unroll
    for (int nt = 0; nt < 8; nt++) {
        oc[nt][0] *= cr0; oc[nt][1] *= cr0;
        oc[nt][2] *= cr1; oc[nt][3] *= cr1;
    }
    #pragma unroll
    for (int nt = 0; nt < 16; nt++) {
        float p0 = rna_tf32(__expf(scr[nt][0] - mn0));
        float p1 = rna_tf32(__expf(scr[nt][1] - mn0));
        float p2 = rna_tf32(__expf(scr[nt][2] - mn1));
        float p3 = rna_tf32(__expf(scr[nt][3] - mn1));
        l0 += p0 + p1; l1 += p2 + p3;
        scr[nt][0] = p0; scr[nt][1] = p1; scr[nt][2] = p2; scr[nt][3] = p3;
    }

    // O += P @ V  (shuffle S-fragment (cols 2t,2t+1) into A-fragment (cols t,t+4))
    const int s1 = (grp << 2) + (tig >> 1);
    const int s2 = s1 + 2;
    const bool odd = (tig & 1) != 0;
    #pragma unroll
    for (int kp = 0; kp < 16; kp++) {
        float t0a = __shfl_sync(0xffffffffu, scr[kp][0], s1);
        float t0b = __shfl_sync(0xffffffffu, scr[kp][1], s1);
        float u0a = __shfl_sync(0xffffffffu, scr[kp][0], s2);
        float u0b = __shfl_sync(0xffffffffu, scr[kp][1], s2);
        float t1a = __shfl_sync(0xffffffffu, scr[kp][2], s1);
        float t1b = __shfl_sync(0xffffffffu, scr[kp][3], s1);
        float u1a = __shfl_sync(0xffffffffu, scr[kp][2], s2);
        float u1b = __shfl_sync(0xffffffffu, scr[kp][3], s2);
        uint32_t pa[4];
        pa[0] = __float_as_uint(odd ? t0b : t0a);
        pa[1] = __float_as_uint(odd ? t1b : t1a);
        pa[2] = __float_as_uint(odd ? u0b : u0a);
        pa[3] = __float_as_uint(odd ? u1b : u1a);
        const float* vb = Vs + (kp * 8 + tig) * ALDV + grp;
        #pragma unroll
        for (int nt = 0; nt < 8; nt++) {
            mma_tf32_16x8x8(oc[nt], pa,
                            __float_as_uint(vb[nt * 8]),
                            __float_as_uint(vb[4 * ALDV + nt * 8]));
        }
    }
}

__global__ __launch_bounds__(256, 1)
void attn_mma_kernel(const float* __restrict__ q,
                     const float* __restrict__ k,
                     const float* __restrict__ v,
                     float* __restrict__ out)
{
    extern __shared__ float sm[];
    float* Qs = sm;
    const int blk = blockIdx.x, h = blockIdx.y, b = blockIdx.z;
    const int tid = threadIdx.x, lane = tid & 31, wid = tid >> 5;
    const int grp = lane >> 2, tig = lane & 3;
    const int r0 = wid * 16;
    const size_t rowbase = (size_t)b * L_ + (size_t)blk * WIN_;

    const uint32_t kvbase = smem_u32(sm + 128 * ALDQ);
    const int BUFB = 128 * (ALDK + ALDV) * 4;   // bytes per K+V buffer

    // stage Q (pre-scaled by 1/8; q already tf32-rounded, /8 is exact)
    #pragma unroll 4
    for (int i = tid; i < 128 * 16; i += 256) {
        int r = i >> 4, c4 = (i & 15) << 2;
        float4 f = *(const float4*)(q + (rowbase + r) * C_ + h * D_ + c4);
        f.x *= 0.125f; f.y *= 0.125f; f.z *= 0.125f; f.w *= 0.125f;
        *(float4*)&Qs[r * ALDQ + c4] = f;
    }

    // stage K/V chunk ci (ci-1 window offset) into buffer buf; zero-fill OOB
    auto stage = [&](int ci, int buf) {
        uint32_t kd = kvbase + buf * BUFB;
        uint32_t vd = kd + 128 * ALDK * 4;
        int base = (blk + ci - 1) * WIN_;
        #pragma unroll 4
        for (int i = tid; i < 128 * 16; i += 256) {
            int r = i >> 4, c4 = (i & 15) << 2;
            int pos = base + r;
            unsigned sz = (pos >= 0 && pos < L_) ? 16u : 0u;
            int posc = pos < 0 ? 0 : (pos >= L_ ? L_ - 1 : pos);
            size_t goff = ((size_t)b * L_ + posc) * C_ + h * D_ + c4;
            cp_async16z(kd + (r * ALDK + c4) * 4, k + goff, sz);
            cp_async16z(vd + (r * ALDV + c4) * 4, v + goff, sz);
        }
        cp_commit();
    };

    stage(0, 0);
    stage(1, 1);

    float oc[8][4];
    #pragma unroll
    for (int nt = 0; nt < 8; nt++)
        #pragma unroll
        for (int e = 0; e < 4; e++) oc[nt][e] = 0.f;
    float m0 = -INFINITY, m1 = -INFINITY, l0 = 0.f, l1 = 0.f;

    const float* Ks0 = sm + 128 * ALDQ;
    const float* Vs0 = Ks0 + 128 * ALDK;
    const float* Ks1 = Ks0 + 128 * (ALDK + ALDV);
    const float* Vs1 = Ks1 + 128 * ALDK;

    asm volatile("cp.async.wait_group 1;" ::: "memory");
    __syncthreads();
    attn_chunk<0>(Qs, Ks0, Vs0, r0, grp, tig, oc, m0, m1, l0, l1);
    __syncthreads();
    stage(2, 0);
    asm volatile("cp.async.wait_group 1;" ::: "memory");
    __syncthreads();
    attn_chunk<1>(Qs, Ks1, Vs1, r0, grp, tig, oc, m0, m1, l0, l1);
    asm volatile("cp.async.wait_group 0;" ::: "memory");
    __syncthreads();
    attn_chunk<2>(Qs, Ks0, Vs0, r0, grp, tig, oc, m0, m1, l0, l1);

    // epilogue: quad-reduce l, normalize, rna-round (consumed by tf32 GEMM)
    l0 += __shfl_xor_sync(0xffffffffu, l0, 1);
    l0 += __shfl_xor_sync(0xffffffffu, l0, 2);
    l1 += __shfl_xor_sync(0xffffffffu, l1, 1);
    l1 += __shfl_xor_sync(0xffffffffu, l1, 2);
    float i0 = 1.0f / l0, i1 = 1.0f / l1;

    size_t oa = (rowbase + r0 + grp) * C_ + h * D_;
    size_t ob = oa + 8 * C_;
    #pragma unroll
    for (int nt = 0; nt < 8; nt++) {
        float2 w0, w1;
        w0.x = rna_tf32(oc[nt][0] * i0); w0.y = rna_tf32(oc[nt][1] * i0);
        w1.x = rna_tf32(oc[nt][2] * i1); w1.y = rna_tf32(oc[nt][3] * i1);
        *(float2*)(out + oa + nt * 8 + tig * 2) = w0;
        *(float2*)(out + ob + nt * 8 + tig * 2) = w1;
    }
}

// ---------------------------------------------------------------------------
extern "C" void kernel_launch(void* const* d_in, const int* in_sizes, int n_in,
                              void* d_out, int out_size)
{
    const float* x  = (const float*)d_in[0];
    const float* wq = (const float*)d_in[1];
    const float* bq = (const float*)d_in[2];
    const float* wk = (const float*)d_in[3];
    const float* bk = (const float*)d_in[4];
    const float* wv = (const float*)d_in[5];
    const float* bv = (const float*)d_in[6];
    const float* wo = (const float*)d_in[7];
    const float* bo = (const float*)d_in[8];
    float* out = (float*)d_out;

    float *q, *k, *v, *att, *xa, *wt;
    cudaGetSymbolAddress((void**)&q,   g_q);
    cudaGetSymbolAddress((void**)&k,   g_k);
    cudaGetSymbolAddress((void**)&v,   g_v);
    cudaGetSymbolAddress((void**)&att, g_att);
    cudaGetSymbolAddress((void**)&xa,  g_xa);
    cudaGetSymbolAddress((void**)&wt,  g_wt);
    float* wtq = wt + 0 * (size_t)C_ * C_;
    float* wtk = wt + 1 * (size_t)C_ * C_;
    float* wtv = wt + 2 * (size_t)C_ * C_;
    float* wto = wt + 3 * (size_t)C_ * C_;

    cvt_rna_kernel<<<(M_ * C_) / 4 / 256, 256>>>(x, xa);
    dim3 tGrid(C_ / 32, C_ / 32), tBlk(32, 8);
    transpose_cvt_kernel<<<tGrid, tBlk>>>(wq, wtq);
    transpose_cvt_kernel<<<tGrid, tBlk>>>(wk, wtk);
    transpose_cvt_kernel<<<tGrid, tBlk>>>(wv, wtv);
    transpose_cvt_kernel<<<tGrid, tBlk>>>(wo, wto);

    cudaFuncSetAttribute(gemm_tf32_kernel<true>,
                         cudaFuncAttributeMaxDynamicSharedMemorySize, GSMEM_BYTES);
    cudaFuncSetAttribute(gemm_tf32_kernel<false>,
                         cudaFuncAttributeMaxDynamicSharedMemorySize, GSMEM_BYTES);
    cudaFuncSetAttribute(attn_mma_kernel,
                         cudaFuncAttributeMaxDynamicSharedMemorySize, ASM_BYTES);

    dim3 gGrid(C_ / GBN, M_ / GBM);   // (8, 64)
    gemm_tf32_kernel<true><<<gGrid, 256, GSMEM_BYTES>>>(xa, wtq, bq, q);
    gemm_tf32_kernel<true><<<gGrid, 256, GSMEM_BYTES>>>(xa, wtk, bk, k);
    gemm_tf32_kernel<true><<<gGrid, 256, GSMEM_BYTES>>>(xa, wtv, bv, v);

    dim3 aGrid(NB_, H_, B_);
    attn_mma_kernel<<<aGrid, 256, ASM_BYTES>>>(q, k, v, att);

    gemm_tf32_kernel<false><<<gGrid, 256, GSMEM_BYTES>>>(att, wto, bo, out);
}

// round 5
// speedup vs baseline: 3.8290x; 1.0260x over previous
#include <cuda_runtime.h>
#include <math.h>
#include <stdint.h>

#define B_   2
#define L_   4096
#define C_   1024
#define H_   16
#define D_   64
#define WIN_ 128
#define NB_  (L_ / WIN_)
#define M_   (B_ * L_)   // 8192 rows
#define NQKV 3072

// ---------------- scratch (device globals; no allocation allowed) ----------
__device__ float g_qkv[(size_t)M_ * NQKV];  // fused q|k|v output
__device__ float g_att[(size_t)M_ * C_];
__device__ float g_xa [(size_t)M_ * C_];    // x converted to tf32 (rna)
__device__ float g_wt [4][(size_t)C_ * C_]; // transposed+rna weights [N][K]; 0..2 = wq|wk|wv concat
__device__ float g_b3 [NQKV];               // concat bias q|k|v

// ---------------------------------------------------------------------------
// helpers
// ---------------------------------------------------------------------------
__device__ __forceinline__ uint32_t smem_u32(const void* p) {
    uint32_t a;
    asm("{ .reg .u64 t; cvta.to.shared.u64 t, %1; cvt.u32.u64 %0, t; }"
        : "=r"(a) : "l"(p));
    return a;
}
__device__ __forceinline__ float rna_tf32(float f) {
    uint32_t u;
    asm("cvt.rna.tf32.f32 %0, %1;" : "=r"(u) : "f"(f));
    return __uint_as_float(u);
}
__device__ __forceinline__ void cp_async16(uint32_t dst, const void* src) {
    asm volatile("cp.async.cg.shared.global [%0], [%1], 16;"
                 :: "r"(dst), "l"(src) : "memory");
}
__device__ __forceinline__ void cp_async16z(uint32_t dst, const void* src, unsigned sz) {
    asm volatile("cp.async.cg.shared.global [%0], [%1], 16, %2;"
                 :: "r"(dst), "l"(src), "r"(sz) : "memory");
}
__device__ __forceinline__ void cp_commit() {
    asm volatile("cp.async.commit_group;" ::: "memory");
}
__device__ __forceinline__ void mma_tf32_16x8x8(float c[4],
                                                const uint32_t a[4],
                                                uint32_t b0, uint32_t b1) {
    asm volatile(
        "mma.sync.aligned.m16n8k8.row.col.f32.tf32.tf32.f32 "
        "{%0,%1,%2,%3}, {%4,%5,%6,%7}, {%8,%9}, {%0,%1,%2,%3};"
        : "+f"(c[0]), "+f"(c[1]), "+f"(c[2]), "+f"(c[3])
        : "r"(a[0]), "r"(a[1]), "r"(a[2]), "r"(a[3]), "r"(b0), "r"(b1));
}

// ---------------------------------------------------------------------------
// elementwise rna-convert
// ---------------------------------------------------------------------------
__global__ void cvt_rna_kernel(const float* __restrict__ in, float* __restrict__ out) {
    size_t i = ((size_t)blockIdx.x * blockDim.x + threadIdx.x) * 4;
    float4 v = *(const float4*)(in + i);
    v.x = rna_tf32(v.x); v.y = rna_tf32(v.y);
    v.z = rna_tf32(v.z); v.w = rna_tf32(v.w);
    *(float4*)(out + i) = v;
}

// transpose W[K,N] -> Wt[N,K] with rna rounding (K=N=1024)
__global__ void transpose_cvt_kernel(const float* __restrict__ W, float* __restrict__ Wt) {
    __shared__ float tile[32][33];
    int x = blockIdx.x * 32 + threadIdx.x;
    int y = blockIdx.y * 32 + threadIdx.y;
    #pragma unroll
    for (int dy = 0; dy < 32; dy += 8)
        tile[threadIdx.y + dy][threadIdx.x] = W[(size_t)(y + dy) * C_ + x];
    __syncthreads();
    int nx = blockIdx.y * 32 + threadIdx.x;
    int ny = blockIdx.x * 32 + threadIdx.y;
    #pragma unroll
    for (int dy = 0; dy < 32; dy += 8)
        Wt[(size_t)(ny + dy) * C_ + nx] = rna_tf32(tile[threadIdx.x][threadIdx.y + dy]);
}

// concat three 1024-float bias vectors
__global__ void bias_concat_kernel(const float* __restrict__ a,
                                   const float* __restrict__ b,
                                   const float* __restrict__ c,
                                   float* __restrict__ out) {
    int i = blockIdx.x * blockDim.x + threadIdx.x;
    out[i]            = a[i];
    out[i + C_]       = b[i];
    out[i + 2 * C_]   = c[i];
}

// ---------------------------------------------------------------------------
// tf32 mma.sync GEMM: Cm[M][NS] tile (128 x 256) = A[M,1024] @ Wt^T + bias
//   8 warps (4M x 2N), warp tile 32x128, BK=32, 4 stages, 1 barrier/k-tile
// ---------------------------------------------------------------------------
#define GBM 128
#define GBN 256
#define GBK 32
#define GSTG 4
#define GLD 36
#define GST_FLOATS ((GBM + GBN) * GLD)        // 13824 floats
#define GSMEM_BYTES (GSTG * GST_FLOATS * 4)   // 221184
#define GNT (C_ / GBK)                        // 32

__device__ __forceinline__ void g_load_stage(const float* __restrict__ A,
                                             const float* __restrict__ Wt,
                                             int row0, int col0, int kt,
                                             uint32_t sstage, int tid)
{
    const int kf = kt * GBK;
    uint32_t aBase = sstage;
    uint32_t bBase = sstage + GBM * GLD * 4;
    #pragma unroll
    for (int it = 0; it < 12; it++) {
        int i = tid + it * 256;               // 0..3071
        if (i < GBM * 8) {
            int r = i >> 3, c = i & 7;
            cp_async16(aBase + r * (GLD * 4) + c * 16,
                       A + (size_t)(row0 + r) * C_ + kf + c * 4);
        } else {
            int j = i - GBM * 8;
            int n = j >> 3, c = j & 7;
            cp_async16(bBase + n * (GLD * 4) + c * 16,
                       Wt + (size_t)(col0 + n) * C_ + kf + c * 4);
        }
    }
    cp_commit();
}

template<bool RNA>
__global__ __launch_bounds__(256, 1)
void gemm_tf32_kernel(const float* __restrict__ A,
                      const float* __restrict__ Wt,
                      const float* __restrict__ bias,
                      float* __restrict__ Cm,
                      int NS)
{
    extern __shared__ float sm[];
    const int tid    = threadIdx.x;
    const int lane   = tid & 31;
    const int wid    = tid >> 5;
    const int warp_m = wid & 3;                // 0..3  -> 32-row slab
    const int warp_n = wid >> 2;               // 0..1  -> 128-col slab
    const int grp    = lane >> 2;
    const int tig    = lane & 3;
    const int row0   = blockIdx.y * GBM;
    const int col0   = blockIdx.x * GBN;

    const uint32_t sbase = smem_u32(sm);
    const float* As = sm;
    const float* Bs = sm + GBM * GLD;

    float cf[2][16][4];
    #pragma unroll
    for (int mt = 0; mt < 2; mt++)
        #pragma unroll
        for (int nt = 0; nt < 16; nt++)
            #pragma unroll
            for (int r = 0; r < 4; r++)
                cf[mt][nt][r] = 0.0f;

    #pragma unroll
    for (int s = 0; s < GSTG - 1; s++)
        g_load_stage(A, Wt, row0, col0, s, sbase + s * GST_FLOATS * 4, tid);

    for (int t = 0; t < GNT; t++) {
        asm volatile("cp.async.wait_group %0;" :: "n"(GSTG - 2));
        __syncthreads();                        // single barrier per k-tile

        int j = t + GSTG - 1;
        if (j < GNT)
            g_load_stage(A, Wt, row0, col0, j,
                         sbase + (j % GSTG) * GST_FLOATS * 4, tid);
        else
            cp_commit();

        const float* as = As + (t % GSTG) * GST_FLOATS;
        const float* bs = Bs + (t % GSTG) * GST_FLOATS;

        #pragma unroll
        for (int ks = 0; ks < 4; ks++) {
            const int k0 = ks * 8;
            uint32_t af[2][4];
            #pragma unroll
            for (int mt = 0; mt < 2; mt++) {
                const float* ap = as + (warp_m * 32 + mt * 16 + grp) * GLD + k0 + tig;
                af[mt][0] = __float_as_uint(ap[0]);
                af[mt][1] = __float_as_uint(ap[8 * GLD]);
                af[mt][2] = __float_as_uint(ap[4]);
                af[mt][3] = __float_as_uint(ap[8 * GLD + 4]);
            }
            #pragma unroll
            for (int nt = 0; nt < 16; nt++) {
                const float* bp = bs + (warp_n * 128 + nt * 8 + grp) * GLD + k0 + tig;
                uint32_t b0 = __float_as_uint(bp[0]);
                uint32_t b1 = __float_as_uint(bp[4]);
                mma_tf32_16x8x8(cf[0][nt], af[0], b0, b1);
                mma_tf32_16x8x8(cf[1][nt], af[1], b0, b1);
            }
        }
    }

    #pragma unroll
    for (int mt = 0; mt < 2; mt++) {
        int rbase = row0 + warp_m * 32 + mt * 16 + grp;
        #pragma unroll
        for (int nt = 0; nt < 16; nt++) {
            int col = col0 + warp_n * 128 + nt * 8 + tig * 2;
            float2 b2 = *(const float2*)(bias + col);
            float2 o0, o1;
            if (RNA) {
                o0.x = rna_tf32(cf[mt][nt][0] + b2.x);  o0.y = rna_tf32(cf[mt][nt][1] + b2.y);
                o1.x = rna_tf32(cf[mt][nt][2] + b2.x);  o1.y = rna_tf32(cf[mt][nt][3] + b2.y);
            } else {
                o0.x = cf[mt][nt][0] + b2.x;  o0.y = cf[mt][nt][1] + b2.y;
                o1.x = cf[mt][nt][2] + b2.x;  o1.y = cf[mt][nt][3] + b2.y;
            }
            *(float2*)(Cm + (size_t)rbase * NS + col)       = o0;
            *(float2*)(Cm + (size_t)(rbase + 8) * NS + col) = o1;
        }
    }
}

// ---------------------------------------------------------------------------
// tensor-core flash attention (reads fused qkv[M][3072]: q|k|v col offsets)
// ---------------------------------------------------------------------------
#define ALDQ 68
#define ALDK 68
#define ALDV 72
#define ASM_FLOATS (128 * ALDQ + 2 * 128 * (ALDK + ALDV))
#define ASM_BYTES  (ASM_FLOATS * 4)   // 178176

template<int CI>
__device__ __forceinline__ void attn_chunk(
    const float* __restrict__ Qs, const float* __restrict__ Ks,
    const float* __restrict__ Vs,
    int r0, int grp, int tig,
    float (&oc)[8][4], float& m0, float& m1, float& l0, float& l1)
{
    float scr[16][4];
    #pragma unroll
    for (int nt = 0; nt < 16; nt++)
        #pragma unroll
        for (int e = 0; e < 4; e++) scr[nt][e] = 0.f;

    #pragma unroll
    for (int ks = 0; ks < 8; ks++) {
        const float* qp = Qs + (r0 + grp) * ALDQ + ks * 8 + tig;
        uint32_t qa[4];
        qa[0] = __float_as_uint(qp[0]);
        qa[1] = __float_as_uint(qp[8 * ALDQ]);
        qa[2] = __float_as_uint(qp[4]);
        qa[3] = __float_as_uint(qp[8 * ALDQ + 4]);
        #pragma unroll
        for (int nt = 0; nt < 16; nt++) {
            const float* kp = Ks + (nt * 8 + grp) * ALDK + ks * 8 + tig;
            mma_tf32_16x8x8(scr[nt], qa,
                            __float_as_uint(kp[0]), __float_as_uint(kp[4]));
        }
    }

    const int ra = r0 + grp, rb = ra + 8;
    if (CI == 0) {
        #pragma unroll
        for (int nt = 0; nt < 16; nt++) {
            int c = nt * 8 + 2 * tig;
            if (c     < ra) scr[nt][0] = -INFINITY;
            if (c + 1 < ra) scr[nt][1] = -INFINITY;
            if (c     < rb) scr[nt][2] = -INFINITY;
            if (c + 1 < rb) scr[nt][3] = -INFINITY;
        }
    }
    if (CI == 2) {
        #pragma unroll
        for (int nt = 0; nt < 16; nt++) {
            int c = nt * 8 + 2 * tig;
            if (c     > ra) scr[nt][0] = -INFINITY;
            if (c + 1 > ra) scr[nt][1] = -INFINITY;
            if (c     > rb) scr[nt][2] = -INFINITY;
            if (c + 1 > rb) scr[nt][3] = -INFINITY;
        }
    }

    float mx0 = -INFINITY, mx1 = -INFINITY;
    #pragma unroll
    for (int nt = 0; nt < 16; nt++) {
        mx0 = fmaxf(mx0, fmaxf(scr[nt][0], scr[nt][1]));
        mx1 = fmaxf(mx1, fmaxf(scr[nt][2], scr[nt][3]));
    }
    mx0 = fmaxf(mx0, __shfl_xor_sync(0xffffffffu, mx0, 1));
    mx0 = fmaxf(mx0, __shfl_xor_sync(0xffffffffu, mx0, 2));
    mx1 = fmaxf(mx1, __shfl_xor_sync(0xffffffffu, mx1, 1));
    mx1 = fmaxf(mx1, __shfl_xor_sync(0xffffffffu, mx1, 2));

    float mn0 = fmaxf(m0, mx0), mn1 = fmaxf(m1, mx1);
    float cr0 = __expf(m0 - mn0), cr1 = __expf(m1 - mn1);
    m0 = mn0; m1 = mn1;
    l0 *= cr0; l1 *= cr1;
    #pragma unroll
    for (int nt = 0; nt < 8; nt++) {
        oc[nt][0] *= cr0; oc[nt][1] *= cr0;
        oc[nt][2] *= cr1; oc[nt][3] *= cr1;
    }
    #pragma unroll
    for (int nt = 0; nt < 16; nt++) {
        float p0 = rna_tf32(__expf(scr[nt][0] - mn0));
        float p1 = rna_tf32(__expf(scr[nt][1] - mn0));
        float p2 = rna_tf32(__expf(scr[nt][2] - mn1));
        float p3 = rna_tf32(__expf(scr[nt][3] - mn1));
        l0 += p0 + p1; l1 += p2 + p3;
        scr[nt][0] = p0; scr[nt][1] = p1; scr[nt][2] = p2; scr[nt][3] = p3;
    }

    const int s1 = (grp << 2) + (tig >> 1);
    const int s2 = s1 + 2;
    const bool odd = (tig & 1) != 0;
    #pragma unroll
    for (int kp = 0; kp < 16; kp++) {
        float t0a = __shfl_sync(0xffffffffu, scr[kp][0], s1);
        float t0b = __shfl_sync(0xffffffffu, scr[kp][1], s1);
        float u0a = __shfl_sync(0xffffffffu, scr[kp][0], s2);
        float u0b = __shfl_sync(0xffffffffu, scr[kp][1], s2);
        float t1a = __shfl_sync(0xffffffffu, scr[kp][2], s1);
        float t1b = __shfl_sync(0xffffffffu, scr[kp][3], s1);
        float u1a = __shfl_sync(0xffffffffu, scr[kp][2], s2);
        float u1b = __shfl_sync(0xffffffffu, scr[kp][3], s2);
        uint32_t pa[4];
        pa[0] = __float_as_uint(odd ? t0b : t0a);
        pa[1] = __float_as_uint(odd ? t1b : t1a);
        pa[2] = __float_as_uint(odd ? u0b : u0a);
        pa[3] = __float_as_uint(odd ? u1b : u1a);
        const float* vb = Vs + (kp * 8 + tig) * ALDV + grp;
        #pragma unroll
        for (int nt = 0; nt < 8; nt++) {
            mma_tf32_16x8x8(oc[nt], pa,
                            __float_as_uint(vb[nt * 8]),
                            __float_as_uint(vb[4 * ALDV + nt * 8]));
        }
    }
}

__global__ __launch_bounds__(256, 1)
void attn_mma_kernel(const float* __restrict__ qkv,
                     float* __restrict__ out)
{
    extern __shared__ float sm[];
    float* Qs = sm;
    const int blk = blockIdx.x, h = blockIdx.y, b = blockIdx.z;
    const int tid = threadIdx.x, lane = tid & 31, wid = tid >> 5;
    const int grp = lane >> 2, tig = lane & 3;
    const int r0 = wid * 16;
    const size_t rowbase = (size_t)b * L_ + (size_t)blk * WIN_;

    const uint32_t kvbase = smem_u32(sm + 128 * ALDQ);
    const int BUFB = 128 * (ALDK + ALDV) * 4;

    const float* q = qkv;
    const float* k = qkv + C_;
    const float* v = qkv + 2 * C_;

    #pragma unroll 4
    for (int i = tid; i < 128 * 16; i += 256) {
        int r = i >> 4, c4 = (i & 15) << 2;
        float4 f = *(const float4*)(q + (rowbase + r) * NQKV + h * D_ + c4);
        f.x *= 0.125f; f.y *= 0.125f; f.z *= 0.125f; f.w *= 0.125f;
        *(float4*)&Qs[r * ALDQ + c4] = f;
    }

    auto stage = [&](int ci, int buf) {
        uint32_t kd = kvbase + buf * BUFB;
        uint32_t vd = kd + 128 * ALDK * 4;
        int base = (blk + ci - 1) * WIN_;
        #pragma unroll 4
        for (int i = tid; i < 128 * 16; i += 256) {
            int r = i >> 4, c4 = (i & 15) << 2;
            int pos = base + r;
            unsigned sz = (pos >= 0 && pos < L_) ? 16u : 0u;
            int posc = pos < 0 ? 0 : (pos >= L_ ? L_ - 1 : pos);
            size_t goff = ((size_t)b * L_ + posc) * NQKV + h * D_ + c4;
            cp_async16z(kd + (r * ALDK + c4) * 4, k + goff, sz);
            cp_async16z(vd + (r * ALDV + c4) * 4, v + goff, sz);
        }
        cp_commit();
    };

    stage(0, 0);
    stage(1, 1);

    float oc[8][4];
    #pragma unroll
    for (int nt = 0; nt < 8; nt++)
        #pragma unroll
        for (int e = 0; e < 4; e++) oc[nt][e] = 0.f;
    float m0 = -INFINITY, m1 = -INFINITY, l0 = 0.f, l1 = 0.f;

    const float* Ks0 = sm + 128 * ALDQ;
    const float* Vs0 = Ks0 + 128 * ALDK;
    const float* Ks1 = Ks0 + 128 * (ALDK + ALDV);
    const float* Vs1 = Ks1 + 128 * ALDK;

    asm volatile("cp.async.wait_group 1;" ::: "memory");
    __syncthreads();
    attn_chunk<0>(Qs, Ks0, Vs0, r0, grp, tig, oc, m0, m1, l0, l1);
    __syncthreads();
    stage(2, 0);
    asm volatile("cp.async.wait_group 1;" ::: "memory");
    __syncthreads();
    attn_chunk<1>(Qs, Ks1, Vs1, r0, grp, tig, oc, m0, m1, l0, l1);
    asm volatile("cp.async.wait_group 0;" ::: "memory");
    __syncthreads();
    attn_chunk<2>(Qs, Ks0, Vs0, r0, grp, tig, oc, m0, m1, l0, l1);

    l0 += __shfl_xor_sync(0xffffffffu, l0, 1);
    l0 += __shfl_xor_sync(0xffffffffu, l0, 2);
    l1 += __shfl_xor_sync(0xffffffffu, l1, 1);
    l1 += __shfl_xor_sync(0xffffffffu, l1, 2);
    float i0 = 1.0f / l0, i1 = 1.0f / l1;

    size_t oa = (rowbase + r0 + grp) * C_ + h * D_;
    size_t ob = oa + 8 * C_;
    #pragma unroll
    for (int nt = 0; nt < 8; nt++) {
        float2 w0, w1;
        w0.x = rna_tf32(oc[nt][0] * i0); w0.y = rna_tf32(oc[nt][1] * i0);
        w1.x = rna_tf32(oc[nt][2] * i1); w1.y = rna_tf32(oc[nt][3] * i1);
        *(float2*)(out + oa + nt * 8 + tig * 2) = w0;
        *(float2*)(out + ob + nt * 8 + tig * 2) = w1;
    }
}

// ---------------------------------------------------------------------------
extern "C" void kernel_launch(void* const* d_in, const int* in_sizes, int n_in,
                              void* d_out, int out_size)
{
    const float* x  = (const float*)d_in[0];
    const float* wq = (const float*)d_in[1];
    const float* bq = (const float*)d_in[2];
    const float* wk = (const float*)d_in[3];
    const float* bk = (const float*)d_in[4];
    const float* wv = (const float*)d_in[5];
    const float* bv = (const float*)d_in[6];
    const float* wo = (const float*)d_in[7];
    const float* bo = (const float*)d_in[8];
    float* out = (float*)d_out;

    float *qkv, *att, *xa, *wt, *b3;
    cudaGetSymbolAddress((void**)&qkv, g_qkv);
    cudaGetSymbolAddress((void**)&att, g_att);
    cudaGetSymbolAddress((void**)&xa,  g_xa);
    cudaGetSymbolAddress((void**)&wt,  g_wt);
    cudaGetSymbolAddress((void**)&b3,  g_b3);
    float* wtq = wt + 0 * (size_t)C_ * C_;
    float* wtk = wt + 1 * (size_t)C_ * C_;
    float* wtv = wt + 2 * (size_t)C_ * C_;
    float* wto = wt + 3 * (size_t)C_ * C_;

    cvt_rna_kernel<<<(M_ * C_) / 4 / 256, 256>>>(x, xa);
    dim3 tGrid(C_ / 32, C_ / 32), tBlk(32, 8);
    transpose_cvt_kernel<<<tGrid, tBlk>>>(wq, wtq);
    transpose_cvt_kernel<<<tGrid, tBlk>>>(wk, wtk);
    transpose_cvt_kernel<<<tGrid, tBlk>>>(wv, wtv);
    transpose_cvt_kernel<<<tGrid, tBlk>>>(wo, wto);
    bias_concat_kernel<<<C_ / 256, 256>>>(bq, bk, bv, b3);

    cudaFuncSetAttribute(gemm_tf32_kernel<true>,
                         cudaFuncAttributeMaxDynamicSharedMemorySize, GSMEM_BYTES);
    cudaFuncSetAttribute(gemm_tf32_kernel<false>,
                         cudaFuncAttributeMaxDynamicSharedMemorySize, GSMEM_BYTES);
    cudaFuncSetAttribute(attn_mma_kernel,
                         cudaFuncAttributeMaxDynamicSharedMemorySize, ASM_BYTES);

    // fused QKV projection: [8192,1024] @ [1024,3072] + b3
    dim3 qkvGrid(NQKV / GBN, M_ / GBM);   // (12, 64)
    gemm_tf32_kernel<true><<<qkvGrid, 256, GSMEM_BYTES>>>(xa, wtq, b3, qkv, NQKV);

    dim3 aGrid(NB_, H_, B_);
    attn_mma_kernel<<<aGrid, 256, ASM_BYTES>>>(qkv, att);

    dim3 oGrid(C_ / GBN, M_ / GBM);       // (4, 64)
    gemm_tf32_kernel<false><<<oGrid, 256, GSMEM_BYTES>>>(att, wto, bo, out, C_);
}